// round 2
// baseline (speedup 1.0000x reference)
#include <cuda_runtime.h>
#include <cstddef>

#define NNODES 30000
#define NEDGES 300000
#define DIN    256
#define DH     128
#define DOUT   64
#define LH     6
#define JKW    (DH * (LH + 1))   // 896

// ---------------- scratch (device globals: no allocs allowed) ----------------
__device__ float g_m[NNODES * DIN];                       // aggregation buffer (max 256 wide)
__device__ float g_jk[(size_t)NNODES * JKW];              // all layer outputs, col-blocked
__device__ float g_p[NNODES * DOUT];                      // jk @ Wout (pre-aggregation)
__device__ float g_deg_out[NNODES], g_deg_in[NNODES];
__device__ float g_isq_out[NNODES], g_isq_in[NNODES];

// ---------------- small utility kernels ----------------
__global__ void k_zero4(float4* __restrict__ p, int n4) {
    int i = blockIdx.x * blockDim.x + threadIdx.x;
    if (i < n4) p[i] = make_float4(0.f, 0.f, 0.f, 0.f);
}

__global__ void k_degree(const int* __restrict__ src, const int* __restrict__ dst) {
    int e = blockIdx.x * blockDim.x + threadIdx.x;
    if (e < NEDGES) {
        atomicAdd(&g_deg_out[src[e]], 1.f);
        atomicAdd(&g_deg_in[dst[e]], 1.f);
    }
}

__global__ void k_rsqrt() {
    int i = blockIdx.x * blockDim.x + threadIdx.x;
    if (i < NNODES) {
        g_isq_out[i] = rsqrtf(fmaxf(g_deg_out[i], 1.f));
        g_isq_in[i]  = rsqrtf(fmaxf(g_deg_in[i],  1.f));
    }
}

__global__ void k_init_out(float* __restrict__ out, const float* __restrict__ bout) {
    int i = blockIdx.x * blockDim.x + threadIdx.x;
    if (i < NNODES * DOUT) out[i] = bout[i & (DOUT - 1)];
}

// ---------------- edge scatter: out[dst] += x[src] * (scale?) ----------------
__device__ __forceinline__ void red_add_v4(float* p, float4 v) {
    asm volatile("red.global.add.v4.f32 [%0], {%1, %2, %3, %4};"
                 :: "l"(p), "f"(v.x), "f"(v.y), "f"(v.z), "f"(v.w)
                 : "memory");
}

template <int D4, bool SCALED>
__global__ __launch_bounds__(256) void k_edge(
    const float* __restrict__ x, int ldx,
    const float* __restrict__ scale,
    const int* __restrict__ src, const int* __restrict__ dst,
    float* __restrict__ out, int ldo)
{
    unsigned idx = blockIdx.x * blockDim.x + threadIdx.x;
    unsigned e = idx / D4;
    unsigned c = idx & (D4 - 1);
    if (e >= NEDGES) return;
    int s = src[e], d = dst[e];
    float4 v = *(const float4*)(x + (size_t)s * ldx + c * 4);
    if (SCALED) {
        float sc = scale[s];
        v.x *= sc; v.y *= sc; v.z *= sc; v.w *= sc;
    }
    red_add_v4(out + (size_t)d * ldo + c * 4, v);
}

// ---------------- register-tiled fp32 GEMM ----------------
// C[M, BN] = op( (A .* rowscale?) @ B + bias? ), single block-column (N == BN)
template <int BM, int BN, int BK, int TM, int TN, bool PRESCALE, bool RELU, bool BIAS>
__global__ __launch_bounds__(256) void k_gemm(
    const float* __restrict__ A, int lda, int M, int K,
    const float* __restrict__ rowscale,
    const float* __restrict__ B,            // K x BN, row-major, ldb == BN
    const float* __restrict__ bias,
    float* __restrict__ C, int ldc)
{
    __shared__ float As[BK][BM];
    __shared__ float Bs[BK][BN];

    const int tid  = threadIdx.x;          // 256 threads
    const int row0 = blockIdx.x * BM;
    constexpr int TX = BN / TN;            // threads along N
    const int tx = tid % TX;
    const int ty = tid / TX;

    static_assert(256 * TM * TN == BM * BN, "thread tiling mismatch");
    constexpr int KQ   = BK / 4;
    constexpr int A_PT = (BM * BK / 4) / 256;
    constexpr int NQ   = BN / 4;
    constexpr int B_PT = (BK * BN / 4) / 256;

    float acc[TM][TN];
#pragma unroll
    for (int i = 0; i < TM; i++)
#pragma unroll
        for (int j = 0; j < TN; j++) acc[i][j] = 0.f;

    for (int k0 = 0; k0 < K; k0 += BK) {
        // load A tile (transposed into smem), with optional row prescale
#pragma unroll
        for (int t = 0; t < A_PT; t++) {
            int id = tid + t * 256;
            int r = id / KQ;
            int q = id % KQ;
            float4 v = make_float4(0.f, 0.f, 0.f, 0.f);
            int gr = row0 + r;
            if (gr < M) {
                v = *(const float4*)(A + (size_t)gr * lda + k0 + q * 4);
                if (PRESCALE) {
                    float sc = rowscale[gr];
                    v.x *= sc; v.y *= sc; v.z *= sc; v.w *= sc;
                }
            }
            As[q * 4 + 0][r] = v.x;
            As[q * 4 + 1][r] = v.y;
            As[q * 4 + 2][r] = v.z;
            As[q * 4 + 3][r] = v.w;
        }
        // load B tile
#pragma unroll
        for (int t = 0; t < B_PT; t++) {
            int id = tid + t * 256;
            int r = id / NQ;
            int c = id % NQ;
            float4 v = *(const float4*)(B + (size_t)(k0 + r) * BN + c * 4);
            *(float4*)&Bs[r][c * 4] = v;
        }
        __syncthreads();

#pragma unroll
        for (int k = 0; k < BK; k++) {
            float ra[TM], rb[TN];
#pragma unroll
            for (int i = 0; i < TM; i++) ra[i] = As[k][ty * TM + i];
#pragma unroll
            for (int j = 0; j < TN; j++) rb[j] = Bs[k][tx * TN + j];
#pragma unroll
            for (int i = 0; i < TM; i++)
#pragma unroll
                for (int j = 0; j < TN; j++)
                    acc[i][j] += ra[i] * rb[j];
        }
        __syncthreads();
    }

#pragma unroll
    for (int i = 0; i < TM; i++) {
        int gr = row0 + ty * TM + i;
        if (gr >= M) continue;
#pragma unroll
        for (int j = 0; j < TN; j++) {
            float v = acc[i][j];
            if (BIAS) v += bias[tx * TN + j];
            if (RELU) v = fmaxf(v, 0.f);
            C[(size_t)gr * ldc + tx * TN + j] = v;
        }
    }
}

// ---------------- launch ----------------
extern "C" void kernel_launch(void* const* d_in, const int* in_sizes, int n_in,
                              void* d_out, int out_size)
{
    const float* feats = (const float*)d_in[0];
    const int*   src   = (const int*)d_in[1];
    const int*   dst   = (const int*)d_in[2];
    const float* W0    = (const float*)d_in[3];
    const float* b0    = (const float*)d_in[4];
    const float* Wh    = (const float*)d_in[5];
    const float* bh    = (const float*)d_in[6];
    const float* Wout  = (const float*)d_in[7];
    const float* bout  = (const float*)d_in[8];
    float* out = (float*)d_out;

    float *m, *jk, *p, *dgo, *dgi, *iso, *isi;
    cudaGetSymbolAddress((void**)&m,   g_m);
    cudaGetSymbolAddress((void**)&jk,  g_jk);
    cudaGetSymbolAddress((void**)&p,   g_p);
    cudaGetSymbolAddress((void**)&dgo, g_deg_out);
    cudaGetSymbolAddress((void**)&dgi, g_deg_in);
    cudaGetSymbolAddress((void**)&iso, g_isq_out);
    cudaGetSymbolAddress((void**)&isi, g_isq_in);

    const int T = 256;
    auto blocks = [](long long n, int t) { return (int)((n + t - 1) / t); };

    // degrees + normalization
    k_zero4<<<blocks(NNODES / 4, T), T>>>((float4*)dgo, NNODES / 4);
    k_zero4<<<blocks(NNODES / 4, T), T>>>((float4*)dgi, NNODES / 4);
    k_zero4<<<blocks((long long)NNODES * DIN / 4, T), T>>>((float4*)m, NNODES * DIN / 4);
    k_degree<<<blocks(NEDGES, T), T>>>(src, dst);
    k_rsqrt<<<blocks(NNODES, T), T>>>();

    const int gemm_blocks = (NNODES + 127) / 128;

    // layer 0: aggregate feats (256 wide) then conv -> jk col 0
    k_edge<DIN / 4, true><<<blocks((long long)NEDGES * (DIN / 4), T), T>>>(
        feats, DIN, iso, src, dst, m, DIN);
    k_gemm<128, 128, 16, 8, 8, true, true, true><<<gemm_blocks, T>>>(
        m, DIN, NNODES, DIN, isi, W0, b0, jk, JKW);

    // layers 1..6: aggregate previous jk column block (128 wide), conv -> next column
    for (int l = 0; l < LH; l++) {
        k_zero4<<<blocks((long long)NNODES * DH / 4, T), T>>>((float4*)m, NNODES * DH / 4);
        k_edge<DH / 4, true><<<blocks((long long)NEDGES * (DH / 4), T), T>>>(
            jk + (size_t)l * DH, JKW, iso, src, dst, m, DH);
        k_gemm<128, 128, 16, 8, 8, true, true, true><<<gemm_blocks, T>>>(
            m, DH, NNODES, DH, isi, Wh + (size_t)l * DH * DH, bh + (size_t)l * DH,
            jk + (size_t)(l + 1) * DH, JKW);
    }

    // output projection BEFORE final aggregation (linearity): p = jk @ Wout
    k_gemm<128, 64, 32, 8, 4, false, false, false><<<gemm_blocks, T>>>(
        jk, JKW, NNODES, JKW, nullptr, Wout, nullptr, p, DOUT);

    // out = bout + segsum(p[src], dst)
    k_init_out<<<blocks(NNODES * DOUT, T), T>>>(out, bout);
    k_edge<DOUT / 4, false><<<blocks((long long)NEDGES * (DOUT / 4), T), T>>>(
        p, DOUT, nullptr, src, dst, out, DOUT);
}

// round 3
// speedup vs baseline: 2.0603x; 2.0603x over previous
#include <cuda_runtime.h>
#include <cstddef>

#define NNODES 30000
#define NEDGES 300000
#define DIN    256
#define DH     128
#define DOUT   64
#define LH     6
#define JKW    (DH * (LH + 1))   // 896
#define NB     ((NNODES + 255) / 256)   // 118 scan blocks

// ---------------- scratch (device globals: no allocs allowed) ----------------
__device__ float g_m[NNODES * DIN];            // aggregation output (widest = 256)
__device__ float g_jk[(size_t)NNODES * JKW];   // all layer outputs, col-blocked
__device__ float g_p[NNODES * DOUT];           // jk @ Wout (pre-aggregation)
__device__ float g_iso[NNODES], g_isi[NNODES];
__device__ int   g_cin[NNODES], g_cout[NNODES];
__device__ int   g_rp[NNODES + 1];             // CSR row pointers (by dst)
__device__ int   g_scan[NNODES];
__device__ int   g_bsum[256];
__device__ int   g_cur[NNODES];
__device__ int   g_csrc[NEDGES];               // CSR column indices (src ids)

// ---------------- CSR build ----------------
__global__ void k_zcnt() {
    int i = blockIdx.x * blockDim.x + threadIdx.x;
    if (i < NNODES) { g_cin[i] = 0; g_cout[i] = 0; }
}

__global__ void k_hist(const int* __restrict__ src, const int* __restrict__ dst) {
    int e = blockIdx.x * blockDim.x + threadIdx.x;
    if (e < NEDGES) {
        atomicAdd(&g_cin[dst[e]], 1);
        atomicAdd(&g_cout[src[e]], 1);
    }
}

__global__ void k_rsqrt() {
    int i = blockIdx.x * blockDim.x + threadIdx.x;
    if (i < NNODES) {
        g_iso[i] = rsqrtf((float)max(g_cout[i], 1));
        g_isi[i] = rsqrtf((float)max(g_cin[i],  1));
    }
}

__global__ void k_scan1() {   // per-block inclusive scan of g_cin
    __shared__ int sh[256];
    int t = threadIdx.x;
    int i = blockIdx.x * 256 + t;
    int v = (i < NNODES) ? g_cin[i] : 0;
    sh[t] = v;
    __syncthreads();
    for (int o = 1; o < 256; o <<= 1) {
        int u = (t >= o) ? sh[t - o] : 0;
        __syncthreads();
        sh[t] += u;
        __syncthreads();
    }
    if (i < NNODES) g_scan[i] = sh[t];
    if (t == 255) g_bsum[blockIdx.x] = sh[255];
}

__global__ void k_scan2() {   // serial exclusive scan of block sums (118 entries)
    if (threadIdx.x == 0) {
        int s = 0;
        for (int b = 0; b < NB; b++) { int v = g_bsum[b]; g_bsum[b] = s; s += v; }
    }
}

__global__ void k_scan3() {
    int i = blockIdx.x * blockDim.x + threadIdx.x;
    if (i < NNODES) {
        g_rp[i + 1] = g_scan[i] + g_bsum[i >> 8];
        if (i == 0) g_rp[0] = 0;
    }
}

__global__ void k_copycur() {
    int i = blockIdx.x * blockDim.x + threadIdx.x;
    if (i < NNODES) g_cur[i] = g_rp[i];
}

__global__ void k_fill(const int* __restrict__ src, const int* __restrict__ dst) {
    int e = blockIdx.x * blockDim.x + threadIdx.x;
    if (e < NEDGES) {
        int pos = atomicAdd(&g_cur[dst[e]], 1);
        g_csrc[pos] = src[e];
    }
}

// ---------------- CSR aggregation: one warp per dst node ----------------
// out[d] = (NORM ? isi[d] : 1) * sum_{s in nbr(d)} (NORM ? iso[s] : 1) * x[s]  (+ bias)
template <int D4, bool NORM, bool BIASED>
__global__ __launch_bounds__(256) void k_agg(
    const float* __restrict__ x, int ldx,
    const float* __restrict__ bias,
    float* __restrict__ out, int ldo)
{
    int w = (int)((blockIdx.x * 256u + threadIdx.x) >> 5);
    int lane = threadIdx.x & 31;
    if (w >= NNODES) return;
    int beg = g_rp[w], end = g_rp[w + 1];
    constexpr int NC = (D4 + 31) / 32;
    float4 acc[NC];
#pragma unroll
    for (int j = 0; j < NC; j++) acc[j] = make_float4(0.f, 0.f, 0.f, 0.f);

    for (int e = beg; e < end; e++) {
        int s = g_csrc[e];
        float sc = NORM ? g_iso[s] : 1.f;
        const float4* xr = (const float4*)(x + (size_t)s * ldx);
#pragma unroll
        for (int j = 0; j < NC; j++) {
            int c = lane + 32 * j;
            if (32 * (j + 1) <= D4 || c < D4) {
                float4 v = xr[c];
                acc[j].x += v.x * sc;
                acc[j].y += v.y * sc;
                acc[j].z += v.z * sc;
                acc[j].w += v.w * sc;
            }
        }
    }
    float si = NORM ? g_isi[w] : 1.f;
    float4* orow = (float4*)(out + (size_t)w * ldo);
#pragma unroll
    for (int j = 0; j < NC; j++) {
        int c = lane + 32 * j;
        if (32 * (j + 1) <= D4 || c < D4) {
            float4 r = acc[j];
            r.x *= si; r.y *= si; r.z *= si; r.w *= si;
            if (BIASED) {
                float4 b = ((const float4*)bias)[c];
                r.x += b.x; r.y += b.y; r.z += b.z; r.w += b.w;
            }
            orow[c] = r;
        }
    }
}

// ---------------- tf32 tensor-core GEMM ----------------
__device__ __forceinline__ unsigned to_tf32(float f) {
    unsigned r;
    asm("cvt.rna.tf32.f32 %0, %1;" : "=r"(r) : "f"(f));
    return r;
}

__device__ __forceinline__ void mma_tf32(float* c, const unsigned* a, const unsigned* b) {
    asm volatile(
        "mma.sync.aligned.m16n8k8.row.col.f32.tf32.tf32.f32 "
        "{%0,%1,%2,%3}, {%4,%5,%6,%7}, {%8,%9}, {%0,%1,%2,%3};"
        : "+f"(c[0]), "+f"(c[1]), "+f"(c[2]), "+f"(c[3])
        : "r"(a[0]), "r"(a[1]), "r"(a[2]), "r"(a[3]), "r"(b[0]), "r"(b[1]));
}

// C[M, BN] = op(A[M, K] @ B[K, BN] + bias), N == BN, B row-major with ldb == BN
template <int BM, int BN, int BK, int WM, int WN, bool RELU, bool BIAS>
__global__ __launch_bounds__(256) void k_gemm_tf32(
    const float* __restrict__ A, int lda, int M, int K,
    const float* __restrict__ B,
    const float* __restrict__ bias,
    float* __restrict__ C, int ldc)
{
    constexpr int AS = BK + 4;     // 36: stride ≡ 4 (mod 32) -> conflict-free A frags
    constexpr int BS = BN + 8;     // ≡ 8 (mod 32) -> conflict-free B frags
    __shared__ unsigned As[BM * AS];
    __shared__ unsigned Bs[BK * BS];

    constexpr int WARPS_N = BN / WN;
    constexpr int WARPS_M = BM / WM;
    static_assert(WARPS_M * WARPS_N == 8, "8 warps");
    constexpr int MT = WM / 16, NT = WN / 8;

    const int tid = threadIdx.x;
    const int wid = tid >> 5, lane = tid & 31;
    const int wn = wid % WARPS_N, wm = wid / WARPS_N;
    const int g = lane >> 2, t = lane & 3;
    const int row0 = blockIdx.x * BM;

    constexpr int KQ = BK / 4;
    constexpr int NQ = BN / 4;
    constexpr int A_PT = BM * BK / 1024;
    constexpr int B_PT = BK * BN / 1024;

    float acc[MT][NT][4] = {};

    for (int k0 = 0; k0 < K; k0 += BK) {
        // A tile: BM x BK, tf32-converted
#pragma unroll
        for (int i = 0; i < A_PT; i++) {
            int id = tid + i * 256;
            int r = id / KQ, q = id % KQ;
            int gr = row0 + r;
            float4 v = make_float4(0.f, 0.f, 0.f, 0.f);
            if (gr < M) v = *(const float4*)(A + (size_t)gr * lda + k0 + q * 4);
            unsigned* p = &As[r * AS + q * 4];
            p[0] = to_tf32(v.x); p[1] = to_tf32(v.y);
            p[2] = to_tf32(v.z); p[3] = to_tf32(v.w);
        }
        // B tile: BK x BN (k-major)
#pragma unroll
        for (int i = 0; i < B_PT; i++) {
            int id = tid + i * 256;
            int r = id / NQ, q = id % NQ;
            float4 v = *(const float4*)(B + (size_t)(k0 + r) * BN + q * 4);
            unsigned* p = &Bs[r * BS + q * 4];
            p[0] = to_tf32(v.x); p[1] = to_tf32(v.y);
            p[2] = to_tf32(v.z); p[3] = to_tf32(v.w);
        }
        __syncthreads();

#pragma unroll
        for (int ks = 0; ks < BK / 8; ks++) {
            unsigned a[MT][4], b[NT][2];
#pragma unroll
            for (int mt = 0; mt < MT; mt++) {
                const unsigned* ap = &As[(wm * WM + mt * 16 + g) * AS + ks * 8 + t];
                a[mt][0] = ap[0];
                a[mt][2] = ap[4];
                a[mt][1] = ap[8 * AS];
                a[mt][3] = ap[8 * AS + 4];
            }
#pragma unroll
            for (int nt = 0; nt < NT; nt++) {
                const unsigned* bp = &Bs[(ks * 8 + t) * BS + wn * WN + nt * 8 + g];
                b[nt][0] = bp[0];
                b[nt][1] = bp[4 * BS];
            }
#pragma unroll
            for (int mt = 0; mt < MT; mt++)
#pragma unroll
                for (int nt = 0; nt < NT; nt++)
                    mma_tf32(acc[mt][nt], a[mt], b[nt]);
        }
        __syncthreads();
    }

    // epilogue
#pragma unroll
    for (int mt = 0; mt < MT; mt++) {
#pragma unroll
        for (int nt = 0; nt < NT; nt++) {
            int n = wn * WN + nt * 8 + 2 * t;
            float bx = 0.f, by = 0.f;
            if (BIAS) { bx = bias[n]; by = bias[n + 1]; }
            int r0 = row0 + wm * WM + mt * 16 + g;
            float vx = acc[mt][nt][0] + bx, vy = acc[mt][nt][1] + by;
            if (RELU) { vx = fmaxf(vx, 0.f); vy = fmaxf(vy, 0.f); }
            if (r0 < M) *(float2*)(C + (size_t)r0 * ldc + n) = make_float2(vx, vy);
            int r1 = r0 + 8;
            float wx = acc[mt][nt][2] + bx, wy = acc[mt][nt][3] + by;
            if (RELU) { wx = fmaxf(wx, 0.f); wy = fmaxf(wy, 0.f); }
            if (r1 < M) *(float2*)(C + (size_t)r1 * ldc + n) = make_float2(wx, wy);
        }
    }
}

// ---------------- launch ----------------
extern "C" void kernel_launch(void* const* d_in, const int* in_sizes, int n_in,
                              void* d_out, int out_size)
{
    const float* feats = (const float*)d_in[0];
    const int*   src   = (const int*)d_in[1];
    const int*   dst   = (const int*)d_in[2];
    const float* W0    = (const float*)d_in[3];
    const float* b0    = (const float*)d_in[4];
    const float* Wh    = (const float*)d_in[5];
    const float* bh    = (const float*)d_in[6];
    const float* Wout  = (const float*)d_in[7];
    const float* bout  = (const float*)d_in[8];
    float* out = (float*)d_out;

    float *m, *jk, *p;
    cudaGetSymbolAddress((void**)&m,  g_m);
    cudaGetSymbolAddress((void**)&jk, g_jk);
    cudaGetSymbolAddress((void**)&p,  g_p);

    const int T = 256;
    const int eb = (NEDGES + T - 1) / T;
    const int agg_blocks = (NNODES * 32 + T - 1) / T;   // warp per node
    const int gemm_blocks = (NNODES + 127) / 128;

    // CSR build + normalization
    k_zcnt<<<NB, T>>>();
    k_hist<<<eb, T>>>(src, dst);
    k_rsqrt<<<NB, T>>>();
    k_scan1<<<NB, T>>>();
    k_scan2<<<1, 32>>>();
    k_scan3<<<NB, T>>>();
    k_copycur<<<NB, T>>>();
    k_fill<<<eb, T>>>(src, dst);

    // layer 0: aggregate feats (256 wide, normalized) then conv -> jk col 0
    k_agg<DIN / 4, true, false><<<agg_blocks, T>>>(feats, DIN, nullptr, m, DIN);
    k_gemm_tf32<128, 128, 32, 64, 32, true, true><<<gemm_blocks, T>>>(
        m, DIN, NNODES, DIN, W0, b0, jk, JKW);

    // layers 1..6
    for (int l = 0; l < LH; l++) {
        k_agg<DH / 4, true, false><<<agg_blocks, T>>>(
            jk + (size_t)l * DH, JKW, nullptr, m, DH);
        k_gemm_tf32<128, 128, 32, 64, 32, true, true><<<gemm_blocks, T>>>(
            m, DH, NNODES, DH, Wh + (size_t)l * DH * DH, bh + (size_t)l * DH,
            jk + (size_t)(l + 1) * DH, JKW);
    }

    // p = jk @ Wout (project before final aggregation, by linearity)
    k_gemm_tf32<128, 64, 32, 32, 32, false, false><<<gemm_blocks, T>>>(
        jk, JKW, NNODES, JKW, Wout, nullptr, p, DOUT);

    // out = bout + segsum(p[src], dst)  (un-normalized)
    k_agg<DOUT / 4, false, true><<<agg_blocks, T>>>(p, DOUT, bout, out, DOUT);
}

// round 7
// speedup vs baseline: 2.6639x; 1.2930x over previous
#include <cuda_runtime.h>
#include <cstddef>

#define NNODES 30000
#define NEDGES 300000
#define DIN    256
#define DH     128
#define DOUT   64
#define LH     6
#define JKW    (DH * (LH + 1))   // 896
#define NB     ((NNODES + 255) / 256)   // 118 scan blocks

// ---------------- scratch (device globals: no allocs allowed) ----------------
__device__ float g_m[NNODES * DH];             // per-layer GEMM output (pre-agg)
__device__ float g_jk[(size_t)NNODES * JKW];   // all layer outputs, col-blocked
__device__ float g_p[NNODES * DOUT];           // jk @ Wout (pre-aggregation)
__device__ float g_iso[NNODES], g_isi[NNODES];
__device__ int   g_cin[NNODES], g_cout[NNODES];
__device__ int   g_rp[NNODES + 1];             // CSR row pointers (by dst)
__device__ int   g_scan[NNODES];
__device__ int   g_bsum[128];
__device__ int   g_cur[NNODES];
__device__ int   g_csrc[NEDGES];               // CSR column indices (src ids)

// ---------------- CSR build ----------------
__global__ void k_zcnt() {
    int i = blockIdx.x * blockDim.x + threadIdx.x;
    if (i < NNODES) { g_cin[i] = 0; g_cout[i] = 0; }
}

__global__ void k_hist(const int* __restrict__ src, const int* __restrict__ dst) {
    int e = blockIdx.x * blockDim.x + threadIdx.x;
    if (e < NEDGES) {
        atomicAdd(&g_cin[dst[e]], 1);
        atomicAdd(&g_cout[src[e]], 1);
    }
}

__global__ void k_scan1() {   // per-block inclusive scan of g_cin
    __shared__ int sh[256];
    int t = threadIdx.x;
    int i = blockIdx.x * 256 + t;
    int v = (i < NNODES) ? g_cin[i] : 0;
    sh[t] = v;
    __syncthreads();
    for (int o = 1; o < 256; o <<= 1) {
        int u = (t >= o) ? sh[t - o] : 0;
        __syncthreads();
        sh[t] += u;
        __syncthreads();
    }
    if (i < NNODES) g_scan[i] = sh[t];
    if (t == 255) g_bsum[blockIdx.x] = sh[255];
}

__global__ void k_scan2() {   // parallel exclusive scan of 118 block sums
    __shared__ int sh[128];
    int t = threadIdx.x;
    int v = (t < NB) ? g_bsum[t] : 0;
    sh[t] = v;
    __syncthreads();
    for (int o = 1; o < 128; o <<= 1) {
        int u = (t >= o) ? sh[t - o] : 0;
        __syncthreads();
        sh[t] += u;
        __syncthreads();
    }
    if (t < NB) g_bsum[t] = sh[t] - v;   // exclusive
}

__global__ void k_scan3() {   // fused: row pointers + cursors + rsqrt norms
    int i = blockIdx.x * blockDim.x + threadIdx.x;
    if (i < NNODES) {
        int cin = g_cin[i];
        int inc = g_scan[i] + g_bsum[i >> 8];
        g_rp[i + 1] = inc;
        if (i == 0) g_rp[0] = 0;
        g_cur[i] = inc - cin;
        g_iso[i] = rsqrtf((float)max(g_cout[i], 1));
        g_isi[i] = rsqrtf((float)max(cin, 1));
    }
}

__global__ void k_fill(const int* __restrict__ src, const int* __restrict__ dst) {
    int e = blockIdx.x * blockDim.x + threadIdx.x;
    if (e < NEDGES) {
        int pos = atomicAdd(&g_cur[dst[e]], 1);
        g_csrc[pos] = src[e];
    }
}

// ---------------- CSR aggregation, width 128: one warp per dst node ----------
// out[d] = relu( isi[d] * sum_{s in nbr(d)} iso[s] * x[s] + bias )
template <bool NORM, bool BIASRELU>
__global__ __launch_bounds__(256) void k_agg128(
    const float* __restrict__ x, int ldx,
    const float* __restrict__ bias,
    float* __restrict__ out, int ldo)
{
    int w = (int)((blockIdx.x * 256u + threadIdx.x) >> 5);
    int lane = threadIdx.x & 31;
    if (w >= NNODES) return;
    int beg = g_rp[w], end = g_rp[w + 1];

    float4 acc = make_float4(0.f, 0.f, 0.f, 0.f);
    int e = beg;
    for (; e + 4 <= end; e += 4) {
        int s0 = g_csrc[e], s1 = g_csrc[e + 1], s2 = g_csrc[e + 2], s3 = g_csrc[e + 3];
        float4 v0 = __ldg((const float4*)(x + (size_t)s0 * ldx) + lane);
        float4 v1 = __ldg((const float4*)(x + (size_t)s1 * ldx) + lane);
        float4 v2 = __ldg((const float4*)(x + (size_t)s2 * ldx) + lane);
        float4 v3 = __ldg((const float4*)(x + (size_t)s3 * ldx) + lane);
        float c0 = NORM ? g_iso[s0] : 1.f;
        float c1 = NORM ? g_iso[s1] : 1.f;
        float c2 = NORM ? g_iso[s2] : 1.f;
        float c3 = NORM ? g_iso[s3] : 1.f;
        acc.x += v0.x * c0 + v1.x * c1 + v2.x * c2 + v3.x * c3;
        acc.y += v0.y * c0 + v1.y * c1 + v2.y * c2 + v3.y * c3;
        acc.z += v0.z * c0 + v1.z * c1 + v2.z * c2 + v3.z * c3;
        acc.w += v0.w * c0 + v1.w * c1 + v2.w * c2 + v3.w * c3;
    }
    for (; e < end; e++) {
        int s = g_csrc[e];
        float4 v = __ldg((const float4*)(x + (size_t)s * ldx) + lane);
        float c = NORM ? g_iso[s] : 1.f;
        acc.x += v.x * c; acc.y += v.y * c; acc.z += v.z * c; acc.w += v.w * c;
    }

    float si = NORM ? g_isi[w] : 1.f;
    acc.x *= si; acc.y *= si; acc.z *= si; acc.w *= si;
    if (BIASRELU) {
        float4 b = ((const float4*)bias)[lane];
        acc.x = fmaxf(acc.x + b.x, 0.f);
        acc.y = fmaxf(acc.y + b.y, 0.f);
        acc.z = fmaxf(acc.z + b.z, 0.f);
        acc.w = fmaxf(acc.w + b.w, 0.f);
    }
    ((float4*)(out + (size_t)w * ldo))[lane] = acc;
}

// width 64 (final): float2 per lane, un-normalized sum + bias
__global__ __launch_bounds__(256) void k_agg64(
    const float* __restrict__ x,
    const float* __restrict__ bias,
    float* __restrict__ out)
{
    int w = (int)((blockIdx.x * 256u + threadIdx.x) >> 5);
    int lane = threadIdx.x & 31;
    if (w >= NNODES) return;
    int beg = g_rp[w], end = g_rp[w + 1];

    float2 acc = make_float2(0.f, 0.f);
    int e = beg;
    for (; e + 4 <= end; e += 4) {
        int s0 = g_csrc[e], s1 = g_csrc[e + 1], s2 = g_csrc[e + 2], s3 = g_csrc[e + 3];
        float2 v0 = __ldg((const float2*)(x + (size_t)s0 * DOUT) + lane);
        float2 v1 = __ldg((const float2*)(x + (size_t)s1 * DOUT) + lane);
        float2 v2 = __ldg((const float2*)(x + (size_t)s2 * DOUT) + lane);
        float2 v3 = __ldg((const float2*)(x + (size_t)s3 * DOUT) + lane);
        acc.x += v0.x + v1.x + v2.x + v3.x;
        acc.y += v0.y + v1.y + v2.y + v3.y;
    }
    for (; e < end; e++) {
        int s = g_csrc[e];
        float2 v = __ldg((const float2*)(x + (size_t)s * DOUT) + lane);
        acc.x += v.x; acc.y += v.y;
    }
    float2 b = ((const float2*)bias)[lane];
    acc.x += b.x; acc.y += b.y;
    ((float2*)(out + (size_t)w * DOUT))[lane] = acc;
}

// ---------------- tf32 tensor-core GEMM (register-staged pipeline) ----------
__device__ __forceinline__ unsigned to_tf32(float f) {
    unsigned r;
    asm("cvt.rna.tf32.f32 %0, %1;" : "=r"(r) : "f"(f));
    return r;
}

__device__ __forceinline__ void mma_tf32(float* c, const unsigned* a, const unsigned* b) {
    asm volatile(
        "mma.sync.aligned.m16n8k8.row.col.f32.tf32.tf32.f32 "
        "{%0,%1,%2,%3}, {%4,%5,%6,%7}, {%8,%9}, {%0,%1,%2,%3};"
        : "+f"(c[0]), "+f"(c[1]), "+f"(c[2]), "+f"(c[3])
        : "r"(a[0]), "r"(a[1]), "r"(a[2]), "r"(a[3]), "r"(b[0]), "r"(b[1]));
}

// C[M, BN] = A[M, K] @ B[K, BN], N == BN, B row-major (ldb == BN). No epilogue ops.
template <int BM, int BN, int BK, int WM, int WN>
__global__ __launch_bounds__(256) void k_gemm_tf32(
    const float* __restrict__ A, int lda, int M, int K,
    const float* __restrict__ B,
    float* __restrict__ C, int ldc)
{
    constexpr int AS = BK + 4;     // stride ≡ 4 (mod 32): conflict-free A frags
    constexpr int BS = BN + 8;     // stride ≡ 8 (mod 32): conflict-free B frags
    __shared__ unsigned As[BM * AS];
    __shared__ unsigned Bs[BK * BS];

    constexpr int WARPS_N = BN / WN;
    static_assert((BM / WM) * WARPS_N == 8, "8 warps");
    constexpr int MT = WM / 16, NT = WN / 8;

    const int tid = threadIdx.x;
    const int wid = tid >> 5, lane = tid & 31;
    const int wn = wid % WARPS_N, wm = wid / WARPS_N;
    const int g = lane >> 2, t = lane & 3;
    const int row0 = blockIdx.x * BM;

    constexpr int KQ = BK / 4;
    constexpr int NQ = BN / 4;
    constexpr int A_PT = BM * BK / 1024;
    constexpr int B_PT = BK * BN / 1024;

    float4 ra[A_PT], rb[B_PT];
    float acc[MT][NT][4] = {};

    // ---- stage 0 loads ----
#pragma unroll
    for (int i = 0; i < A_PT; i++) {
        int id = tid + i * 256;
        int r = id / KQ, q = id % KQ;
        int gr = row0 + r;
        ra[i] = (gr < M) ? *(const float4*)(A + (size_t)gr * lda + q * 4)
                         : make_float4(0.f, 0.f, 0.f, 0.f);
    }
#pragma unroll
    for (int i = 0; i < B_PT; i++) {
        int id = tid + i * 256;
        int r = id / NQ, q = id % NQ;
        rb[i] = *(const float4*)(B + (size_t)r * BN + q * 4);
    }

#pragma unroll 1
    for (int k0 = 0; k0 < K; k0 += BK) {
        // ---- commit staged regs to smem (tf32-converted) ----
#pragma unroll
        for (int i = 0; i < A_PT; i++) {
            int id = tid + i * 256;
            int r = id / KQ, q = id % KQ;
            unsigned* p = &As[r * AS + q * 4];
            p[0] = to_tf32(ra[i].x); p[1] = to_tf32(ra[i].y);
            p[2] = to_tf32(ra[i].z); p[3] = to_tf32(ra[i].w);
        }
#pragma unroll
        for (int i = 0; i < B_PT; i++) {
            int id = tid + i * 256;
            int r = id / NQ, q = id % NQ;
            unsigned* p = &Bs[r * BS + q * 4];
            p[0] = to_tf32(rb[i].x); p[1] = to_tf32(rb[i].y);
            p[2] = to_tf32(rb[i].z); p[3] = to_tf32(rb[i].w);
        }
        __syncthreads();

        // ---- prefetch next tile into regs (overlaps with MMA below) ----
        int kn = k0 + BK;
        if (kn < K) {
#pragma unroll
            for (int i = 0; i < A_PT; i++) {
                int id = tid + i * 256;
                int r = id / KQ, q = id % KQ;
                int gr = row0 + r;
                ra[i] = (gr < M) ? *(const float4*)(A + (size_t)gr * lda + kn + q * 4)
                                 : make_float4(0.f, 0.f, 0.f, 0.f);
            }
#pragma unroll
            for (int i = 0; i < B_PT; i++) {
                int id = tid + i * 256;
                int r = id / NQ, q = id % NQ;
                rb[i] = *(const float4*)(B + (size_t)(kn + r) * BN + q * 4);
            }
        }

        // ---- compute from smem ----
#pragma unroll
        for (int ks = 0; ks < BK / 8; ks++) {
            unsigned a[MT][4], b[NT][2];
#pragma unroll
            for (int mt = 0; mt < MT; mt++) {
                const unsigned* ap = &As[(wm * WM + mt * 16 + g) * AS + ks * 8 + t];
                a[mt][0] = ap[0];
                a[mt][2] = ap[4];
                a[mt][1] = ap[8 * AS];
                a[mt][3] = ap[8 * AS + 4];
            }
#pragma unroll
            for (int nt = 0; nt < NT; nt++) {
                const unsigned* bp = &Bs[(ks * 8 + t) * BS + wn * WN + nt * 8 + g];
                b[nt][0] = bp[0];
                b[nt][1] = bp[4 * BS];
            }
#pragma unroll
            for (int mt = 0; mt < MT; mt++)
#pragma unroll
                for (int nt = 0; nt < NT; nt++)
                    mma_tf32(acc[mt][nt], a[mt], b[nt]);
        }
        __syncthreads();
    }

    // ---- epilogue (plain store; bias/relu live in the agg kernels) ----
#pragma unroll
    for (int mt = 0; mt < MT; mt++) {
#pragma unroll
        for (int nt = 0; nt < NT; nt++) {
            int n = wn * WN + nt * 8 + 2 * t;
            int r0 = row0 + wm * WM + mt * 16 + g;
            if (r0 < M)
                *(float2*)(C + (size_t)r0 * ldc + n) =
                    make_float2(acc[mt][nt][0], acc[mt][nt][1]);
            int r1 = r0 + 8;
            if (r1 < M)
                *(float2*)(C + (size_t)r1 * ldc + n) =
                    make_float2(acc[mt][nt][2], acc[mt][nt][3]);
        }
    }
}

// ---------------- launch ----------------
extern "C" void kernel_launch(void* const* d_in, const int* in_sizes, int n_in,
                              void* d_out, int out_size)
{
    const float* feats = (const float*)d_in[0];
    const int*   src   = (const int*)d_in[1];
    const int*   dst   = (const int*)d_in[2];
    const float* W0    = (const float*)d_in[3];
    const float* b0    = (const float*)d_in[4];
    const float* Wh    = (const float*)d_in[5];
    const float* bh    = (const float*)d_in[6];
    const float* Wout  = (const float*)d_in[7];
    const float* bout  = (const float*)d_in[8];
    float* out = (float*)d_out;

    float *m, *jk, *p;
    cudaGetSymbolAddress((void**)&m,  g_m);
    cudaGetSymbolAddress((void**)&jk, g_jk);
    cudaGetSymbolAddress((void**)&p,  g_p);

    const int T = 256;
    const int eb = (NEDGES + T - 1) / T;
    const int agg_blocks = (NNODES * 32 + T - 1) / T;   // warp per node
    const int gemm_blocks = (NNODES + 127) / 128;

    // CSR build + normalization (6 launches)
    k_zcnt<<<NB, T>>>();
    k_hist<<<eb, T>>>(src, dst);
    k_scan1<<<NB, T>>>();
    k_scan2<<<1, 128>>>();
    k_scan3<<<NB, T>>>();
    k_fill<<<eb, T>>>(src, dst);

    // layer 0 (GEMM-first: aggregate at width 128 instead of 256)
    k_gemm_tf32<128, 128, 32, 64, 32><<<gemm_blocks, T>>>(
        feats, DIN, NNODES, DIN, W0, m, DH);
    k_agg128<true, true><<<agg_blocks, T>>>(m, DH, b0, jk, JKW);

    // hidden layers 1..6 (GEMM-first, uniform)
    for (int l = 0; l < LH; l++) {
        k_gemm_tf32<128, 128, 32, 64, 32><<<gemm_blocks, T>>>(
            jk + (size_t)l * DH, JKW, NNODES, DH, Wh + (size_t)l * DH * DH, m, DH);
        k_agg128<true, true><<<agg_blocks, T>>>(
            m, DH, bh + (size_t)l * DH, jk + (size_t)(l + 1) * DH, JKW);
    }

    // p = jk @ Wout (project before final aggregation, by linearity)
    k_gemm_tf32<128, 64, 32, 32, 32><<<gemm_blocks, T>>>(
        jk, JKW, NNODES, JKW, Wout, p, DOUT);

    // out = bout + segsum(p[src], dst)
    k_agg64<<<agg_blocks, T>>>(p, bout, out);
}

// round 9
// speedup vs baseline: 2.7627x; 1.0371x over previous
#include <cuda_runtime.h>
#include <cstdint>
#include <cstddef>

#define NNODES 30000
#define NEDGES 300000
#define DIN    256
#define DH     128
#define DOUT   64
#define LH     6
#define JKW    (DH * (LH + 1))   // 896
#define NB     ((NNODES + 255) / 256)   // 118 scan blocks

// ---------------- scratch (device globals: no allocs allowed) ----------------
__device__ float g_m[NNODES * DH];             // per-layer GEMM output (pre-agg)
__device__ float g_jk[(size_t)NNODES * JKW];   // all layer outputs, col-blocked
__device__ float g_p[NNODES * DOUT];           // jk @ Wout (pre-aggregation)
__device__ float g_iso[NNODES], g_isi[NNODES];
__device__ int   g_cin[NNODES], g_cout[NNODES];
__device__ int   g_rp[NNODES + 1];             // CSR row pointers (by dst)
__device__ int   g_scan[NNODES];
__device__ int   g_bsum[128];
__device__ int   g_cur[NNODES];
__device__ int   g_csrc[NEDGES];               // CSR column indices (src ids)

// ---------------- CSR build ----------------
__global__ void k_hist(const int* __restrict__ src, const int* __restrict__ dst) {
    int e = blockIdx.x * blockDim.x + threadIdx.x;
    if (e < NEDGES) {
        atomicAdd(&g_cin[dst[e]], 1);
        atomicAdd(&g_cout[src[e]], 1);
    }
}

__global__ void k_scan1() {
    __shared__ int sh[256];
    int t = threadIdx.x;
    int i = blockIdx.x * 256 + t;
    int v = (i < NNODES) ? g_cin[i] : 0;
    sh[t] = v;
    __syncthreads();
    for (int o = 1; o < 256; o <<= 1) {
        int u = (t >= o) ? sh[t - o] : 0;
        __syncthreads();
        sh[t] += u;
        __syncthreads();
    }
    if (i < NNODES) g_scan[i] = sh[t];
    if (t == 255) g_bsum[blockIdx.x] = sh[255];
}

__global__ void k_scan2() {
    __shared__ int sh[128];
    int t = threadIdx.x;
    int v = (t < NB) ? g_bsum[t] : 0;
    sh[t] = v;
    __syncthreads();
    for (int o = 1; o < 128; o <<= 1) {
        int u = (t >= o) ? sh[t - o] : 0;
        __syncthreads();
        sh[t] += u;
        __syncthreads();
    }
    if (t < NB) g_bsum[t] = sh[t] - v;   // exclusive
}

__global__ void k_scan3() {
    int i = blockIdx.x * blockDim.x + threadIdx.x;
    if (i < NNODES) {
        int cin = g_cin[i];
        int inc = g_scan[i] + g_bsum[i >> 8];
        g_rp[i + 1] = inc;
        if (i == 0) g_rp[0] = 0;
        g_cur[i] = inc - cin;
        g_iso[i] = rsqrtf((float)max(g_cout[i], 1));
        g_isi[i] = rsqrtf((float)max(cin, 1));
    }
}

__global__ void k_fill(const int* __restrict__ src, const int* __restrict__ dst) {
    int e = blockIdx.x * blockDim.x + threadIdx.x;
    if (e < NEDGES) {
        int pos = atomicAdd(&g_cur[dst[e]], 1);
        g_csrc[pos] = src[e];
    }
}

// ---------------- CSR aggregation, width 128: one warp per dst node ----------
template <bool NORM, bool BIASRELU>
__global__ __launch_bounds__(256) void k_agg128(
    const float* __restrict__ x, int ldx,
    const float* __restrict__ bias,
    float* __restrict__ out, int ldo)
{
    int w = (int)((blockIdx.x * 256u + threadIdx.x) >> 5);
    int lane = threadIdx.x & 31;
    if (w >= NNODES) return;
    int beg = g_rp[w], end = g_rp[w + 1];

    float4 acc = make_float4(0.f, 0.f, 0.f, 0.f);
    int e = beg;
    for (; e + 4 <= end; e += 4) {
        int s0 = g_csrc[e], s1 = g_csrc[e + 1], s2 = g_csrc[e + 2], s3 = g_csrc[e + 3];
        float4 v0 = __ldg((const float4*)(x + (size_t)s0 * ldx) + lane);
        float4 v1 = __ldg((const float4*)(x + (size_t)s1 * ldx) + lane);
        float4 v2 = __ldg((const float4*)(x + (size_t)s2 * ldx) + lane);
        float4 v3 = __ldg((const float4*)(x + (size_t)s3 * ldx) + lane);
        float c0 = NORM ? g_iso[s0] : 1.f;
        float c1 = NORM ? g_iso[s1] : 1.f;
        float c2 = NORM ? g_iso[s2] : 1.f;
        float c3 = NORM ? g_iso[s3] : 1.f;
        acc.x += v0.x * c0 + v1.x * c1 + v2.x * c2 + v3.x * c3;
        acc.y += v0.y * c0 + v1.y * c1 + v2.y * c2 + v3.y * c3;
        acc.z += v0.z * c0 + v1.z * c1 + v2.z * c2 + v3.z * c3;
        acc.w += v0.w * c0 + v1.w * c1 + v2.w * c2 + v3.w * c3;
    }
    for (; e < end; e++) {
        int s = g_csrc[e];
        float4 v = __ldg((const float4*)(x + (size_t)s * ldx) + lane);
        float c = NORM ? g_iso[s] : 1.f;
        acc.x += v.x * c; acc.y += v.y * c; acc.z += v.z * c; acc.w += v.w * c;
    }

    float si = NORM ? g_isi[w] : 1.f;
    acc.x *= si; acc.y *= si; acc.z *= si; acc.w *= si;
    if (BIASRELU) {
        float4 b = ((const float4*)bias)[lane];
        acc.x = fmaxf(acc.x + b.x, 0.f);
        acc.y = fmaxf(acc.y + b.y, 0.f);
        acc.z = fmaxf(acc.z + b.z, 0.f);
        acc.w = fmaxf(acc.w + b.w, 0.f);
    }
    ((float4*)(out + (size_t)w * ldo))[lane] = acc;
}

__global__ __launch_bounds__(256) void k_agg64(
    const float* __restrict__ x,
    const float* __restrict__ bias,
    float* __restrict__ out)
{
    int w = (int)((blockIdx.x * 256u + threadIdx.x) >> 5);
    int lane = threadIdx.x & 31;
    if (w >= NNODES) return;
    int beg = g_rp[w], end = g_rp[w + 1];

    float2 acc = make_float2(0.f, 0.f);
    int e = beg;
    for (; e + 4 <= end; e += 4) {
        int s0 = g_csrc[e], s1 = g_csrc[e + 1], s2 = g_csrc[e + 2], s3 = g_csrc[e + 3];
        float2 v0 = __ldg((const float2*)(x + (size_t)s0 * DOUT) + lane);
        float2 v1 = __ldg((const float2*)(x + (size_t)s1 * DOUT) + lane);
        float2 v2 = __ldg((const float2*)(x + (size_t)s2 * DOUT) + lane);
        float2 v3 = __ldg((const float2*)(x + (size_t)s3 * DOUT) + lane);
        acc.x += v0.x + v1.x + v2.x + v3.x;
        acc.y += v0.y + v1.y + v2.y + v3.y;
    }
    for (; e < end; e++) {
        int s = g_csrc[e];
        float2 v = __ldg((const float2*)(x + (size_t)s * DOUT) + lane);
        acc.x += v.x; acc.y += v.y;
    }
    float2 b = ((const float2*)bias)[lane];
    acc.x += b.x; acc.y += b.y;
    ((float2*)(out + (size_t)w * DOUT))[lane] = acc;
}

// ---------------- tf32 tensor-core GEMM, cp.async 3-stage pipeline ----------
__device__ __forceinline__ unsigned to_tf32(float f) {
    unsigned r;
    asm("cvt.rna.tf32.f32 %0, %1;" : "=r"(r) : "f"(f));
    return r;
}

__device__ __forceinline__ void mma_tf32(float* c, const unsigned* a, const unsigned* b) {
    asm volatile(
        "mma.sync.aligned.m16n8k8.row.col.f32.tf32.tf32.f32 "
        "{%0,%1,%2,%3}, {%4,%5,%6,%7}, {%8,%9}, {%0,%1,%2,%3};"
        : "+f"(c[0]), "+f"(c[1]), "+f"(c[2]), "+f"(c[3])
        : "r"(a[0]), "r"(a[1]), "r"(a[2]), "r"(a[3]), "r"(b[0]), "r"(b[1]));
}

__device__ __forceinline__ void cpa16(uint32_t dst, const void* src, int sz) {
    asm volatile("cp.async.cg.shared.global [%0], [%1], 16, %2;"
                 :: "r"(dst), "l"(src), "r"(sz) : "memory");
}
__device__ __forceinline__ void cpa_commit() {
    asm volatile("cp.async.commit_group;" ::: "memory");
}
template <int Nw>
__device__ __forceinline__ void cpa_wait() {
    asm volatile("cp.async.wait_group %0;" :: "n"(Nw) : "memory");
}

// C[M, BN] = A[M, K] @ B[K, BN], N == BN, B row-major (ldb == BN).
template <int BM, int BN, int BK, int WM, int WN, int STAGES>
__global__ __launch_bounds__(256) void k_gemm_cp(
    const float* __restrict__ A, int lda, int M, int K,
    const float* __restrict__ B,
    float* __restrict__ C, int ldc)
{
    constexpr int AS = BK + 4;     // fp32 elems; stride ≡ 4 (mod 32): conflict-free frags
    constexpr int BS = BN + 8;     // ≡ 8 (mod 32)
    extern __shared__ float smem[];
    float* Asm = smem;                              // STAGES * BM * AS
    float* Bsm = smem + STAGES * BM * AS;           // STAGES * BK * BS
    const uint32_t sA = (uint32_t)__cvta_generic_to_shared(Asm);
    const uint32_t sB = (uint32_t)__cvta_generic_to_shared(Bsm);

    constexpr int WARPS_N = BN / WN;
    static_assert((BM / WM) * WARPS_N == 8, "8 warps");
    constexpr int MT = WM / 16, NT = WN / 8;
    constexpr int KQ = BK / 4;
    constexpr int NQ = BN / 4;
    constexpr int A_PT = BM * BK / 1024;
    constexpr int B_PT = BK * BN / 1024;

    const int tid = threadIdx.x;
    const int wid = tid >> 5, lane = tid & 31;
    const int wn = wid % WARPS_N, wm = wid / WARPS_N;
    const int g = lane >> 2, t = lane & 3;
    const int row0 = blockIdx.x * BM;
    const int S = K / BK;

    // prefetch one k-tile into pipeline slot
    auto prefetch = [&](int s, int slot) {
        const int k0 = s * BK;
#pragma unroll
        for (int i = 0; i < A_PT; i++) {
            int id = tid + i * 256;
            int r = id / KQ, q = id % KQ;
            int gr = row0 + r;
            uint32_t d = sA + ((slot * BM + r) * AS + q * 4) * 4;
            cpa16(d, A + (size_t)gr * lda + k0 + q * 4, (gr < M) ? 16 : 0);
        }
#pragma unroll
        for (int i = 0; i < B_PT; i++) {
            int id = tid + i * 256;
            int r = id / NQ, q = id % NQ;
            uint32_t d = sB + ((slot * BK + r) * BS + q * 4) * 4;
            cpa16(d, B + (size_t)(k0 + r) * BN + q * 4, 16);
        }
        cpa_commit();
    };

    float acc[MT][NT][4] = {};

#pragma unroll
    for (int s = 0; s < STAGES - 1; s++) prefetch(s, s);

#pragma unroll 1
    for (int s = 0; s < S; s++) {
        cpa_wait<STAGES - 2>();
        __syncthreads();                 // stage s ready; slot (s-1)%STAGES free

        int sn = s + STAGES - 1;
        if (sn < S) prefetch(sn, sn % STAGES);
        else        cpa_commit();        // empty group keeps wait-count arithmetic valid

        const int slot = s % STAGES;
        const float* Aslab = Asm + slot * BM * AS;
        const float* Bslab = Bsm + slot * BK * BS;
#pragma unroll
        for (int ks = 0; ks < BK / 8; ks++) {
            unsigned a[MT][4], b[NT][2];
#pragma unroll
            for (int mt = 0; mt < MT; mt++) {
                const float* ap = &Aslab[(wm * WM + mt * 16 + g) * AS + ks * 8 + t];
                a[mt][0] = to_tf32(ap[0]);
                a[mt][2] = to_tf32(ap[4]);
                a[mt][1] = to_tf32(ap[8 * AS]);
                a[mt][3] = to_tf32(ap[8 * AS + 4]);
            }
#pragma unroll
            for (int nt = 0; nt < NT; nt++) {
                const float* bp = &Bslab[(ks * 8 + t) * BS + wn * WN + nt * 8 + g];
                b[nt][0] = to_tf32(bp[0]);
                b[nt][1] = to_tf32(bp[4 * BS]);
            }
#pragma unroll
            for (int mt = 0; mt < MT; mt++)
#pragma unroll
                for (int nt = 0; nt < NT; nt++)
                    mma_tf32(acc[mt][nt], a[mt], b[nt]);
        }
    }

    // epilogue (plain store; bias/relu live in the agg kernels)
#pragma unroll
    for (int mt = 0; mt < MT; mt++) {
#pragma unroll
        for (int nt = 0; nt < NT; nt++) {
            int n = wn * WN + nt * 8 + 2 * t;
            int r0 = row0 + wm * WM + mt * 16 + g;
            if (r0 < M)
                *(float2*)(C + (size_t)r0 * ldc + n) =
                    make_float2(acc[mt][nt][0], acc[mt][nt][1]);
            int r1 = r0 + 8;
            if (r1 < M)
                *(float2*)(C + (size_t)r1 * ldc + n) =
                    make_float2(acc[mt][nt][2], acc[mt][nt][3]);
        }
    }
}

// ---------------- launch ----------------
extern "C" void kernel_launch(void* const* d_in, const int* in_sizes, int n_in,
                              void* d_out, int out_size)
{
    const float* feats = (const float*)d_in[0];
    const int*   src   = (const int*)d_in[1];
    const int*   dst   = (const int*)d_in[2];
    const float* W0    = (const float*)d_in[3];
    const float* b0    = (const float*)d_in[4];
    const float* Wh    = (const float*)d_in[5];
    const float* bh    = (const float*)d_in[6];
    const float* Wout  = (const float*)d_in[7];
    const float* bout  = (const float*)d_in[8];
    float* out = (float*)d_out;

    float *m, *jk, *p;
    int *cin, *cout;
    cudaGetSymbolAddress((void**)&m,    g_m);
    cudaGetSymbolAddress((void**)&jk,   g_jk);
    cudaGetSymbolAddress((void**)&p,    g_p);
    cudaGetSymbolAddress((void**)&cin,  g_cin);
    cudaGetSymbolAddress((void**)&cout, g_cout);

    // dynamic smem: STAGES * (BM*AS + BK*BS) floats
    const int SM128 = 3 * (128 * 36 + 32 * 136) * 4;   // 107520
    const int SM64  = 3 * (128 * 36 + 32 * 72)  * 4;   // 82944
    cudaFuncSetAttribute((const void*)k_gemm_cp<128, 128, 32, 64, 32, 3>,
                         cudaFuncAttributeMaxDynamicSharedMemorySize, SM128);
    cudaFuncSetAttribute((const void*)k_gemm_cp<128, 64, 32, 32, 32, 3>,
                         cudaFuncAttributeMaxDynamicSharedMemorySize, SM64);

    const int T = 256;
    const int eb = (NEDGES + T - 1) / T;
    const int agg_blocks = (NNODES * 32 + T - 1) / T;
    const int gemm_blocks = (NNODES + 127) / 128;   // 235

    // CSR build (memset nodes replace the zero kernel)
    cudaMemsetAsync(cin,  0, NNODES * sizeof(int));
    cudaMemsetAsync(cout, 0, NNODES * sizeof(int));
    k_hist<<<eb, T>>>(src, dst);
    k_scan1<<<NB, T>>>();
    k_scan2<<<1, 128>>>();
    k_scan3<<<NB, T>>>();
    k_fill<<<eb, T>>>(src, dst);

    // layer 0 (GEMM-first: project feats, then aggregate at width 128)
    k_gemm_cp<128, 128, 32, 64, 32, 3><<<gemm_blocks, T, SM128>>>(
        feats, DIN, NNODES, DIN, W0, m, DH);
    k_agg128<true, true><<<agg_blocks, T>>>(m, DH, b0, jk, JKW);

    // hidden layers 1..6
    for (int l = 0; l < LH; l++) {
        k_gemm_cp<128, 128, 32, 64, 32, 3><<<gemm_blocks, T, SM128>>>(
            jk + (size_t)l * DH, JKW, NNODES, DH, Wh + (size_t)l * DH * DH, m, DH);
        k_agg128<true, true><<<agg_blocks, T>>>(
            m, DH, bh + (size_t)l * DH, jk + (size_t)(l + 1) * DH, JKW);
    }

    // p = jk @ Wout (project before final aggregation, by linearity)
    k_gemm_cp<128, 64, 32, 32, 32, 3><<<gemm_blocks, T, SM64>>>(
        jk, JKW, NNODES, JKW, Wout, p, DOUT);

    // out = bout + segsum(p[src], dst)
    k_agg64<<<agg_blocks, T>>>(p, bout, out);
}

// round 10
// speedup vs baseline: 2.8468x; 1.0304x over previous
#include <cuda_runtime.h>
#include <cuda_fp16.h>
#include <cstdint>
#include <cstddef>

#define NNODES 30000
#define NEDGES 300000
#define DIN    256
#define DH     128
#define DOUT   64
#define LH     6
#define JKW    (DH * (LH + 1))   // 896
#define NB     ((NNODES + 255) / 256)   // 118 scan blocks

// ---------------- scratch (device globals: no allocs allowed) ----------------
__device__ __half g_feat16[(size_t)NNODES * DIN];   // fp16 copy of input feats
__device__ __half g_m16[(size_t)NNODES * DH];       // per-layer GEMM output (pre-agg)
__device__ __half g_jk16[(size_t)NNODES * JKW];     // all layer outputs, col-blocked
__device__ __half g_p16[(size_t)NNODES * DOUT];     // jk @ Wout (pre-aggregation)
__device__ float g_iso[NNODES], g_isi[NNODES];
__device__ int   g_cin[NNODES], g_cout[NNODES];
__device__ int   g_rp[NNODES + 1];                  // CSR row pointers (by dst)
__device__ int   g_scan[NNODES];
__device__ int   g_bsum[128];
__device__ int   g_cur[NNODES];
__device__ int   g_csrc[NEDGES];                    // CSR column indices (src ids)

// ---------------- CSR build ----------------
__global__ void k_hist(const int* __restrict__ src, const int* __restrict__ dst) {
    int e = blockIdx.x * blockDim.x + threadIdx.x;
    if (e < NEDGES) {
        atomicAdd(&g_cin[dst[e]], 1);
        atomicAdd(&g_cout[src[e]], 1);
    }
}

__global__ void k_scan1() {
    __shared__ int sh[256];
    int t = threadIdx.x;
    int i = blockIdx.x * 256 + t;
    int v = (i < NNODES) ? g_cin[i] : 0;
    sh[t] = v;
    __syncthreads();
    for (int o = 1; o < 256; o <<= 1) {
        int u = (t >= o) ? sh[t - o] : 0;
        __syncthreads();
        sh[t] += u;
        __syncthreads();
    }
    if (i < NNODES) g_scan[i] = sh[t];
    if (t == 255) g_bsum[blockIdx.x] = sh[255];
}

__global__ void k_scan2() {
    __shared__ int sh[128];
    int t = threadIdx.x;
    int v = (t < NB) ? g_bsum[t] : 0;
    sh[t] = v;
    __syncthreads();
    for (int o = 1; o < 128; o <<= 1) {
        int u = (t >= o) ? sh[t - o] : 0;
        __syncthreads();
        sh[t] += u;
        __syncthreads();
    }
    if (t < NB) g_bsum[t] = sh[t] - v;   // exclusive
}

__global__ void k_scan3() {
    int i = blockIdx.x * blockDim.x + threadIdx.x;
    if (i < NNODES) {
        int cin = g_cin[i];
        int inc = g_scan[i] + g_bsum[i >> 8];
        g_rp[i + 1] = inc;
        if (i == 0) g_rp[0] = 0;
        g_cur[i] = inc - cin;
        g_iso[i] = rsqrtf((float)max(g_cout[i], 1));
        g_isi[i] = rsqrtf((float)max(cin, 1));
    }
}

__global__ void k_fill(const int* __restrict__ src, const int* __restrict__ dst) {
    int e = blockIdx.x * blockDim.x + threadIdx.x;
    if (e < NEDGES) {
        int pos = atomicAdd(&g_cur[dst[e]], 1);
        g_csrc[pos] = src[e];
    }
}

// ---------------- feats fp32 -> fp16 ----------------
__global__ __launch_bounds__(256) void k_f2h(const float* __restrict__ in, int n4) {
    int i = blockIdx.x * blockDim.x + threadIdx.x;
    if (i < n4) {
        float4 v = ((const float4*)in)[i];
        ((__half2*)g_feat16)[2 * i]     = __floats2half2_rn(v.x, v.y);
        ((__half2*)g_feat16)[2 * i + 1] = __floats2half2_rn(v.z, v.w);
    }
}

// ---------------- CSR aggregation, width 128 (fp16 in/out, fp32 math) -------
// jk[d] = relu( isi[d] * sum_{s in nbr(d)} iso[s] * m[s] + bias )
__global__ __launch_bounds__(256) void k_agg128(
    const __half* __restrict__ x,               // [N][DH] fp16
    const float* __restrict__ bias,
    __half* __restrict__ out, int ldo)          // halves
{
    int w = (int)((blockIdx.x * 256u + threadIdx.x) >> 5);
    int lane = threadIdx.x & 31;
    if (w >= NNODES) return;
    int beg = g_rp[w], end = g_rp[w + 1];

    float4 acc = make_float4(0.f, 0.f, 0.f, 0.f);
    int e = beg;
    for (; e + 4 <= end; e += 4) {
        int s0 = g_csrc[e], s1 = g_csrc[e + 1], s2 = g_csrc[e + 2], s3 = g_csrc[e + 3];
        float2 r0 = __ldg((const float2*)(x + (size_t)s0 * DH) + lane);
        float2 r1 = __ldg((const float2*)(x + (size_t)s1 * DH) + lane);
        float2 r2 = __ldg((const float2*)(x + (size_t)s2 * DH) + lane);
        float2 r3 = __ldg((const float2*)(x + (size_t)s3 * DH) + lane);
        float c0 = g_iso[s0], c1 = g_iso[s1], c2 = g_iso[s2], c3 = g_iso[s3];
        float2 a0 = __half22float2(*(__half2*)&r0.x), b0 = __half22float2(*(__half2*)&r0.y);
        float2 a1 = __half22float2(*(__half2*)&r1.x), b1 = __half22float2(*(__half2*)&r1.y);
        float2 a2 = __half22float2(*(__half2*)&r2.x), b2 = __half22float2(*(__half2*)&r2.y);
        float2 a3 = __half22float2(*(__half2*)&r3.x), b3 = __half22float2(*(__half2*)&r3.y);
        acc.x += a0.x * c0 + a1.x * c1 + a2.x * c2 + a3.x * c3;
        acc.y += a0.y * c0 + a1.y * c1 + a2.y * c2 + a3.y * c3;
        acc.z += b0.x * c0 + b1.x * c1 + b2.x * c2 + b3.x * c3;
        acc.w += b0.y * c0 + b1.y * c1 + b2.y * c2 + b3.y * c3;
    }
    for (; e < end; e++) {
        int s = g_csrc[e];
        float2 r = __ldg((const float2*)(x + (size_t)s * DH) + lane);
        float c = g_iso[s];
        float2 a = __half22float2(*(__half2*)&r.x), b = __half22float2(*(__half2*)&r.y);
        acc.x += a.x * c; acc.y += a.y * c; acc.z += b.x * c; acc.w += b.y * c;
    }

    float si = g_isi[w];
    float4 b = ((const float4*)bias)[lane];
    float vx = fmaxf(acc.x * si + b.x, 0.f);
    float vy = fmaxf(acc.y * si + b.y, 0.f);
    float vz = fmaxf(acc.z * si + b.z, 0.f);
    float vw = fmaxf(acc.w * si + b.w, 0.f);
    __half2* orow = (__half2*)(out + (size_t)w * ldo);
    orow[2 * lane]     = __floats2half2_rn(vx, vy);
    orow[2 * lane + 1] = __floats2half2_rn(vz, vw);
}

// width 64 (final): half2 per lane gather, fp32 out = bias + unnormalized sum
__global__ __launch_bounds__(256) void k_agg64(
    const __half* __restrict__ x,
    const float* __restrict__ bias,
    float* __restrict__ out)
{
    int w = (int)((blockIdx.x * 256u + threadIdx.x) >> 5);
    int lane = threadIdx.x & 31;
    if (w >= NNODES) return;
    int beg = g_rp[w], end = g_rp[w + 1];

    float2 acc = make_float2(0.f, 0.f);
    int e = beg;
    for (; e + 4 <= end; e += 4) {
        int s0 = g_csrc[e], s1 = g_csrc[e + 1], s2 = g_csrc[e + 2], s3 = g_csrc[e + 3];
        unsigned u0 = __ldg((const unsigned*)(x + (size_t)s0 * DOUT) + lane);
        unsigned u1 = __ldg((const unsigned*)(x + (size_t)s1 * DOUT) + lane);
        unsigned u2 = __ldg((const unsigned*)(x + (size_t)s2 * DOUT) + lane);
        unsigned u3 = __ldg((const unsigned*)(x + (size_t)s3 * DOUT) + lane);
        float2 f0 = __half22float2(*(__half2*)&u0);
        float2 f1 = __half22float2(*(__half2*)&u1);
        float2 f2 = __half22float2(*(__half2*)&u2);
        float2 f3 = __half22float2(*(__half2*)&u3);
        acc.x += f0.x + f1.x + f2.x + f3.x;
        acc.y += f0.y + f1.y + f2.y + f3.y;
    }
    for (; e < end; e++) {
        int s = g_csrc[e];
        unsigned u = __ldg((const unsigned*)(x + (size_t)s * DOUT) + lane);
        float2 f = __half22float2(*(__half2*)&u);
        acc.x += f.x; acc.y += f.y;
    }
    float2 b = ((const float2*)bias)[lane];
    ((float2*)(out + (size_t)w * DOUT))[lane] = make_float2(acc.x + b.x, acc.y + b.y);
}

// ------- tf32 tensor-core GEMM, fp16 A operand, cp.async 3-stage pipeline ----
__device__ __forceinline__ unsigned to_tf32(float f) {
    unsigned r;
    asm("cvt.rna.tf32.f32 %0, %1;" : "=r"(r) : "f"(f));
    return r;
}

__device__ __forceinline__ void mma_tf32(float* c, const unsigned* a, const unsigned* b) {
    asm volatile(
        "mma.sync.aligned.m16n8k8.row.col.f32.tf32.tf32.f32 "
        "{%0,%1,%2,%3}, {%4,%5,%6,%7}, {%8,%9}, {%0,%1,%2,%3};"
        : "+f"(c[0]), "+f"(c[1]), "+f"(c[2]), "+f"(c[3])
        : "r"(a[0]), "r"(a[1]), "r"(a[2]), "r"(a[3]), "r"(b[0]), "r"(b[1]));
}

__device__ __forceinline__ void cpa16(uint32_t dst, const void* src, int sz) {
    asm volatile("cp.async.cg.shared.global [%0], [%1], 16, %2;"
                 :: "r"(dst), "l"(src), "r"(sz) : "memory");
}
__device__ __forceinline__ void cpa_commit() {
    asm volatile("cp.async.commit_group;" ::: "memory");
}
template <int Nw>
__device__ __forceinline__ void cpa_wait() {
    asm volatile("cp.async.wait_group %0;" :: "n"(Nw) : "memory");
}

// C[M, BN] = A[M, K] @ B[K, BN];  A fp16, B fp32 row-major (ldb == BN), C fp16.
template <int BM, int BN, int BK, int WM, int WN, int STAGES>
__global__ __launch_bounds__(256) void k_gemm_h(
    const __half* __restrict__ A, int lda, int M, int K,
    const float* __restrict__ B,
    __half* __restrict__ C, int ldc)
{
    constexpr int ASH = BK + 8;    // halves; 80-B row stride -> conflict-free frags
    constexpr int BS  = BN + 8;    // fp32;   ≡ 8 (mod 32)
    extern __shared__ char smraw[];
    __half* Asm = (__half*)smraw;                               // STAGES*BM*ASH halves
    float*  Bsm = (float*)(smraw + (size_t)STAGES * BM * ASH * 2);
    const uint32_t sA = (uint32_t)__cvta_generic_to_shared(Asm);
    const uint32_t sB = (uint32_t)__cvta_generic_to_shared(Bsm);

    constexpr int WARPS_N = BN / WN;
    static_assert((BM / WM) * WARPS_N == 8, "8 warps");
    constexpr int MT = WM / 16, NT = WN / 8;
    constexpr int KC = BK / 8;                   // 16B half-chunks per A row
    constexpr int NQ = BN / 4;
    constexpr int A_PT = BM * KC / 256;
    constexpr int B_PT = BK * BN / 1024;

    const int tid = threadIdx.x;
    const int wid = tid >> 5, lane = tid & 31;
    const int wn = wid % WARPS_N, wm = wid / WARPS_N;
    const int g = lane >> 2, t = lane & 3;
    const int row0 = blockIdx.x * BM;
    const int S = K / BK;

    auto prefetch = [&](int s, int slot) {
        const int k0 = s * BK;
#pragma unroll
        for (int i = 0; i < A_PT; i++) {
            int id = tid + i * 256;
            int r = id / KC, q = id % KC;
            int gr = row0 + r;
            uint32_t d = sA + ((slot * BM + r) * ASH + q * 8) * 2;
            cpa16(d, A + (size_t)gr * lda + k0 + q * 8, (gr < M) ? 16 : 0);
        }
#pragma unroll
        for (int i = 0; i < B_PT; i++) {
            int id = tid + i * 256;
            int r = id / NQ, q = id % NQ;
            uint32_t d = sB + ((slot * BK + r) * BS + q * 4) * 4;
            cpa16(d, B + (size_t)(k0 + r) * BN + q * 4, 16);
        }
        cpa_commit();
    };

    float acc[MT][NT][4] = {};

#pragma unroll
    for (int s = 0; s < STAGES - 1; s++) prefetch(s, s);

#pragma unroll 1
    for (int s = 0; s < S; s++) {
        cpa_wait<STAGES - 2>();
        __syncthreads();

        int sn = s + STAGES - 1;
        if (sn < S) prefetch(sn, sn % STAGES);
        else        cpa_commit();

        const int slot = s % STAGES;
        const __half* Aslab = Asm + (size_t)slot * BM * ASH;
        const float*  Bslab = Bsm + (size_t)slot * BK * BS;
#pragma unroll
        for (int ks = 0; ks < BK / 8; ks++) {
            unsigned a[MT][4], b[NT][2];
#pragma unroll
            for (int mt = 0; mt < MT; mt++) {
                const __half* ap = &Aslab[(wm * WM + mt * 16 + g) * ASH + ks * 8 + t];
                a[mt][0] = to_tf32(__half2float(ap[0]));
                a[mt][2] = to_tf32(__half2float(ap[4]));
                a[mt][1] = to_tf32(__half2float(ap[8 * ASH]));
                a[mt][3] = to_tf32(__half2float(ap[8 * ASH + 4]));
            }
#pragma unroll
            for (int nt = 0; nt < NT; nt++) {
                const float* bp = &Bslab[(ks * 8 + t) * BS + wn * WN + nt * 8 + g];
                b[nt][0] = to_tf32(bp[0]);
                b[nt][1] = to_tf32(bp[4 * BS]);
            }
#pragma unroll
            for (int mt = 0; mt < MT; mt++)
#pragma unroll
                for (int nt = 0; nt < NT; nt++)
                    mma_tf32(acc[mt][nt], a[mt], b[nt]);
        }
    }

    // epilogue: half2 stores (bias/relu live in the agg kernels)
#pragma unroll
    for (int mt = 0; mt < MT; mt++) {
#pragma unroll
        for (int nt = 0; nt < NT; nt++) {
            int n = wn * WN + nt * 8 + 2 * t;
            int r0 = row0 + wm * WM + mt * 16 + g;
            if (r0 < M)
                *(__half2*)(C + (size_t)r0 * ldc + n) =
                    __floats2half2_rn(acc[mt][nt][0], acc[mt][nt][1]);
            int r1 = r0 + 8;
            if (r1 < M)
                *(__half2*)(C + (size_t)r1 * ldc + n) =
                    __floats2half2_rn(acc[mt][nt][2], acc[mt][nt][3]);
        }
    }
}

// ---------------- launch ----------------
extern "C" void kernel_launch(void* const* d_in, const int* in_sizes, int n_in,
                              void* d_out, int out_size)
{
    const float* feats = (const float*)d_in[0];
    const int*   src   = (const int*)d_in[1];
    const int*   dst   = (const int*)d_in[2];
    const float* W0    = (const float*)d_in[3];
    const float* b0    = (const float*)d_in[4];
    const float* Wh    = (const float*)d_in[5];
    const float* bh    = (const float*)d_in[6];
    const float* Wout  = (const float*)d_in[7];
    const float* bout  = (const float*)d_in[8];
    float* out = (float*)d_out;

    __half *f16, *m, *jk, *p;
    int *cin, *cout;
    cudaGetSymbolAddress((void**)&f16,  g_feat16);
    cudaGetSymbolAddress((void**)&m,    g_m16);
    cudaGetSymbolAddress((void**)&jk,   g_jk16);
    cudaGetSymbolAddress((void**)&p,    g_p16);
    cudaGetSymbolAddress((void**)&cin,  g_cin);
    cudaGetSymbolAddress((void**)&cout, g_cout);

    // dynamic smem: STAGES * (BM*ASH*2 + BK*BS*4) bytes
    const int SM128 = 3 * (128 * 40 * 2 + 32 * 136 * 4);  // 82944
    const int SM64  = 3 * (128 * 40 * 2 + 32 * 72  * 4);  // 58368
    cudaFuncSetAttribute((const void*)k_gemm_h<128, 128, 32, 64, 32, 3>,
                         cudaFuncAttributeMaxDynamicSharedMemorySize, SM128);
    cudaFuncSetAttribute((const void*)k_gemm_h<128, 64, 32, 32, 32, 3>,
                         cudaFuncAttributeMaxDynamicSharedMemorySize, SM64);

    const int T = 256;
    const int eb = (NEDGES + T - 1) / T;
    const int agg_blocks = (NNODES * 32 + T - 1) / T;
    const int gemm_blocks = (NNODES + 127) / 128;   // 235

    // CSR build + input conversion
    cudaMemsetAsync(cin,  0, NNODES * sizeof(int));
    cudaMemsetAsync(cout, 0, NNODES * sizeof(int));
    k_f2h<<<(NNODES * DIN / 4 + T - 1) / T, T>>>(feats, NNODES * DIN / 4);
    k_hist<<<eb, T>>>(src, dst);
    k_scan1<<<NB, T>>>();
    k_scan2<<<1, 128>>>();
    k_scan3<<<NB, T>>>();
    k_fill<<<eb, T>>>(src, dst);

    // layer 0 (GEMM-first: project feats, then aggregate at width 128)
    k_gemm_h<128, 128, 32, 64, 32, 3><<<gemm_blocks, T, SM128>>>(
        f16, DIN, NNODES, DIN, W0, m, DH);
    k_agg128<<<agg_blocks, T>>>(m, b0, jk, JKW);

    // hidden layers 1..6
    for (int l = 0; l < LH; l++) {
        k_gemm_h<128, 128, 32, 64, 32, 3><<<gemm_blocks, T, SM128>>>(
            jk + (size_t)l * DH, JKW, NNODES, DH, Wh + (size_t)l * DH * DH, m, DH);
        k_agg128<<<agg_blocks, T>>>(m, bh + (size_t)l * DH, jk + (size_t)(l + 1) * DH, JKW);
    }

    // p = jk @ Wout (project before final aggregation, by linearity)
    k_gemm_h<128, 64, 32, 32, 32, 3><<<gemm_blocks, T, SM64>>>(
        jk, JKW, NNODES, JKW, Wout, p, DOUT);

    // out = bout + segsum(p[src], dst)
    k_agg64<<<agg_blocks, T>>>(p, bout, out);
}